// round 11
// baseline (speedup 1.0000x reference)
#include <cuda_runtime.h>
#include <cuda_bf16.h>
#include <cstdint>

#define DEV_INLINE __device__ __forceinline__

// ---------------- problem sizes ----------------
#define BB   4
#define SSZ  2048
#define NP   8
#define DD   1024
#define HH   16
#define HDIM 64
#define MQ   (BB*SSZ)       // 8192 rows (current)

// ---------------- scratch (device globals; no allocs allowed) ----------------
__device__ __align__(256) __nv_bfloat16 g_cur [(size_t)MQ * DD];
__device__ __align__(256) __nv_bfloat16 g_wq  [(size_t)DD * DD];
__device__ __align__(256) __nv_bfloat16 g_wkt [(size_t)DD * DD];   // [h][i=1024][j=64]
__device__ __align__(256) __nv_bfloat16 g_wv  [(size_t)DD * DD];
__device__ __align__(256) __nv_bfloat16 g_wo  [(size_t)DD * DD];
__device__ __align__(256) __nv_bfloat16 g_q   [(size_t)MQ * DD];
__device__ __align__(256) __nv_bfloat16 g_qk  [(size_t)HH * MQ * DD];  // [h][bs][i] 256MB
__device__ __align__(256) __nv_bfloat16 g_hm  [(size_t)HH * MQ * DD];  // [h][bs][d] 256MB
__device__ __align__(256) __nv_bfloat16 g_ao  [(size_t)MQ * DD];

// ---------------- helpers ----------------
DEV_INLINE uint32_t smem_u32(const void* p) {
    uint32_t a;
    asm("{ .reg .u64 t; cvta.to.shared.u64 t, %1; cvt.u32.u64 %0, t; }" : "=r"(a) : "l"(p));
    return a;
}
#define CP_ASYNC16(sa, g) \
    asm volatile("cp.async.cg.shared.global [%0], [%1], 16;" :: "r"(sa), "l"(g))
#define CP_COMMIT() asm volatile("cp.async.commit_group;" ::: "memory")
#define SWZ128(x) ((x) ^ (((x) >> 3) & 0x70))

DEV_INLINE void ldmatrix_x4(uint32_t* r, uint32_t addr) {
    asm volatile("ldmatrix.sync.aligned.m8n8.x4.shared.b16 {%0,%1,%2,%3}, [%4];"
                 : "=r"(r[0]), "=r"(r[1]), "=r"(r[2]), "=r"(r[3]) : "r"(addr));
}
DEV_INLINE void ldmatrix_x2(uint32_t& r0, uint32_t& r1, uint32_t addr) {
    asm volatile("ldmatrix.sync.aligned.m8n8.x2.shared.b16 {%0,%1}, [%2];"
                 : "=r"(r0), "=r"(r1) : "r"(addr));
}
DEV_INLINE void mma16816(float* c, const uint32_t* a, uint32_t b0, uint32_t b1) {
    asm volatile("mma.sync.aligned.m16n8k16.row.col.f32.bf16.bf16.f32 "
                 "{%0,%1,%2,%3}, {%4,%5,%6,%7}, {%8,%9}, {%0,%1,%2,%3};"
                 : "+f"(c[0]), "+f"(c[1]), "+f"(c[2]), "+f"(c[3])
                 : "r"(a[0]), "r"(a[1]), "r"(a[2]), "r"(a[3]), "r"(b0), "r"(b1));
}
DEV_INLINE uint32_t pack_bf16(float lo, float hi) {
    uint32_t r;
    asm("cvt.rn.bf16x2.f32 %0, %1, %2;" : "=r"(r) : "f"(hi), "f"(lo));
    return r;
}
DEV_INLINE float2 bf2_to_f2(uint32_t u) {
    __nv_bfloat162 h = *reinterpret_cast<__nv_bfloat162*>(&u);
    return make_float2(__bfloat162float(h.x), __bfloat162float(h.y));
}

// ---------------- merged fp32 -> bf16 conversion (cur + Wq + Wv + Wo) ----------------
#define CUR_CHUNKS (MQ * DD / 4)        // 2097152
#define W_CHUNKS   (DD * DD / 4)        // 262144
__global__ void cvt_all(const float* __restrict__ cur, const float* __restrict__ wq,
                        const float* __restrict__ wv, const float* __restrict__ wo,
                        __nv_bfloat16* __restrict__ ocur, __nv_bfloat16* __restrict__ owq,
                        __nv_bfloat16* __restrict__ owv, __nv_bfloat16* __restrict__ owo) {
    int i = blockIdx.x * blockDim.x + threadIdx.x;
    const float* src;
    __nv_bfloat16* dst;
    int off;
    if (i < CUR_CHUNKS) { src = cur; dst = ocur; off = i; }
    else {
        int j = i - CUR_CHUNKS;
        int wsel = j >> 18;
        off = j & (W_CHUNKS - 1);
        src = (wsel == 0) ? wq : (wsel == 1) ? wv : wo;
        dst = (wsel == 0) ? owq : (wsel == 1) ? owv : owo;
    }
    float4 f = reinterpret_cast<const float4*>(src)[off];
    uint2 p;
    p.x = pack_bf16(f.x, f.y);
    p.y = pack_bf16(f.z, f.w);
    reinterpret_cast<uint2*>(dst)[off] = p;
}

// ---------------- Wk transpose: wkt[h][i][j] = Wk[h*64+j][i] ----------------
__global__ void __launch_bounds__(256) transp_wk(const float* __restrict__ wk,
                                                 __nv_bfloat16* __restrict__ wkt) {
    __shared__ float ts[64][65];
    int h = blockIdx.x & 15, ib = blockIdx.x >> 4;
    int tid = threadIdx.x;
    #pragma unroll
    for (int r = 0; r < 16; r++) {
        int idx = tid + 256 * r;
        int j = idx >> 6, il = idx & 63;
        ts[j][il] = wk[(size_t)(h * 64 + j) * DD + ib * 64 + il];
    }
    __syncthreads();
    #pragma unroll
    for (int r = 0; r < 16; r++) {
        int idx = tid + 256 * r;
        int il = idx >> 6, j = idx & 63;
        wkt[((size_t)h * DD + ib * 64 + il) * 64 + j] = __float2bfloat16(ts[j][il]);
    }
}

// ---------------- main HMMA GEMM (128x256, KC=64, 4-stage) ----------------
static constexpr int TM = 128, TN = 256, KC = 64, KSTAGES = DD / KC;  // 16
static constexpr int A_BYTES = 128 * 128;
static constexpr int B_BYTES = 256 * 128;
static constexpr int STAGE_BYTES = A_BYTES + B_BYTES;  // 48 KB
static constexpr int NSTAGE = 4;
static constexpr int GEMM_SMEM = NSTAGE * STAGE_BYTES;  // 192 KB

DEV_INLINE void load_stage(uint32_t sb, int buf,
                           const __nv_bfloat16* __restrict__ A,
                           const __nv_bfloat16* __restrict__ W,
                           int mt, int ntW, int k0, int tid) {
    uint32_t abase = sb + buf * STAGE_BYTES;
    uint32_t bbase = abase + A_BYTES;
    const char* Ag = reinterpret_cast<const char*>(A + (size_t)mt * TM * DD + k0);
    const char* Bg = reinterpret_cast<const char*>(W + (size_t)ntW * TN * DD + k0);
    #pragma unroll
    for (int i = 0; i < 4; i++) {
        int v = tid + 256 * i;
        int row = v >> 3, c8 = v & 7;
        uint32_t off = (uint32_t)(row * 128 + c8 * 16);
        CP_ASYNC16(abase + SWZ128(off), Ag + (size_t)row * (DD * 2) + c8 * 16);
    }
    #pragma unroll
    for (int i = 0; i < 8; i++) {
        int v = tid + 256 * i;
        int row = v >> 3, c8 = v & 7;
        uint32_t off = (uint32_t)(row * 128 + c8 * 16);
        CP_ASYNC16(bbase + SWZ128(off), Bg + (size_t)row * (DD * 2) + c8 * 16);
    }
}

template <bool OUT_F32>
__global__ void __launch_bounds__(256, 1)
gemm_hmma(const __nv_bfloat16* __restrict__ A, const __nv_bfloat16* __restrict__ W,
          __nv_bfloat16* __restrict__ Cb, float* __restrict__ Cf,
          const float* __restrict__ resid) {
    extern __shared__ char smem[];
    uint32_t sb = smem_u32(smem);
    int tid = threadIdx.x;
    int lane = tid & 31, wid = tid >> 5;
    int wm = wid & 1, wn = wid >> 1;
    int ntW = blockIdx.x & 3;
    int mt = blockIdx.x >> 2;

    float acc[4][8][4];
    #pragma unroll
    for (int i = 0; i < 4; i++)
        #pragma unroll
        for (int j = 0; j < 8; j++)
            #pragma unroll
            for (int r = 0; r < 4; r++) acc[i][j][r] = 0.f;

    #pragma unroll
    for (int s = 0; s < NSTAGE - 1; s++) {
        load_stage(sb, s, A, W, mt, ntW, s * KC, tid);
        CP_COMMIT();
    }

    for (int s = 0; s < KSTAGES; s++) {
        if (s <= KSTAGES - 3)      asm volatile("cp.async.wait_group 2;" ::: "memory");
        else if (s == KSTAGES - 2) asm volatile("cp.async.wait_group 1;" ::: "memory");
        else                       asm volatile("cp.async.wait_group 0;" ::: "memory");
        __syncthreads();

        if (s + NSTAGE - 1 < KSTAGES) {
            load_stage(sb, (s + NSTAGE - 1) & (NSTAGE - 1), A, W, mt, ntW,
                       (s + NSTAGE - 1) * KC, tid);
            CP_COMMIT();
        }

        int buf = s & (NSTAGE - 1);
        uint32_t abase = sb + buf * STAGE_BYTES;
        uint32_t bbase = abase + A_BYTES;
        #pragma unroll
        for (int k16 = 0; k16 < 4; k16++) {
            uint32_t af[4][4];
            #pragma unroll
            for (int i = 0; i < 4; i++) {
                int row = wm * 64 + i * 16 + (lane & 15);
                uint32_t off = (uint32_t)(row * 128 + k16 * 32 + (lane >> 4) * 16);
                ldmatrix_x4(af[i], abase + SWZ128(off));
            }
            uint32_t bfr[4][4];
            #pragma unroll
            for (int j2 = 0; j2 < 4; j2++) {
                int nrow = wn * 64 + j2 * 16 + (lane & 7) + ((lane >> 4) << 3);
                uint32_t off = (uint32_t)(nrow * 128 + k16 * 32 + ((lane >> 3) & 1) * 16);
                ldmatrix_x4(bfr[j2], bbase + SWZ128(off));
            }
            #pragma unroll
            for (int i = 0; i < 4; i++)
                #pragma unroll
                for (int j = 0; j < 8; j++)
                    mma16816(acc[i][j], af[i], bfr[j >> 1][(j & 1) * 2], bfr[j >> 1][(j & 1) * 2 + 1]);
        }
        __syncthreads();
    }

    int rbase = mt * TM + wm * 64 + (lane >> 2);
    int cbase = ntW * TN + wn * 64 + (lane & 3) * 2;
    #pragma unroll
    for (int i = 0; i < 4; i++) {
        #pragma unroll
        for (int half = 0; half < 2; half++) {
            int row = rbase + i * 16 + half * 8;
            size_t base = (size_t)row * DD + cbase;
            if (OUT_F32) {
                #pragma unroll
                for (int j = 0; j < 8; j++) {
                    size_t idx = base + j * 8;
                    float2 rs = *reinterpret_cast<const float2*>(resid + idx);
                    float2 o;
                    o.x = acc[i][j][half * 2 + 0] + rs.x;
                    o.y = acc[i][j][half * 2 + 1] + rs.y;
                    *reinterpret_cast<float2*>(Cf + idx) = o;
                }
            } else {
                #pragma unroll
                for (int j = 0; j < 8; j++) {
                    uint32_t p = pack_bf16(acc[i][j][half * 2 + 0], acc[i][j][half * 2 + 1]);
                    *reinterpret_cast<uint32_t*>(Cb + base + j * 8) = p;
                }
            }
        }
    }
}

// ---------------- qk fold (TM=128, head-major output, staged coalesced epilogue) ----------------
// qk[h][bs][i] = sum_j q[bs][h*64+j] * wkt[h][i][j]
static constexpr int QF_A = 128 * 128;              // 16 KB
static constexpr int QF_B = 256 * 128;              // 32 KB
static constexpr int QF_OUT = 128 * 528;            // 67584
static constexpr int QF_SMEM = QF_A + 2 * QF_B + QF_OUT;   // 149504

__global__ void __launch_bounds__(256, 1) qk_fold2(
    const __nv_bfloat16* __restrict__ q,    // [8192][1024]
    const __nv_bfloat16* __restrict__ wkt,  // [16][1024][64]
    __nv_bfloat16* __restrict__ qk,         // [16][8192][1024]
    int mt0)
{
    extern __shared__ char smem[];
    uint32_t sA = smem_u32(smem);
    uint32_t sB0 = sA + QF_A;
    uint32_t sOut = sB0 + 2 * QF_B;
    int tid = threadIdx.x;
    int lane = tid & 31, wid = tid >> 5;
    int wm = wid & 1, wn = wid >> 1;       // 2(M) x 4(N)
    int mt = blockIdx.x + mt0, h = blockIdx.y;

    {
        const char* Ag = reinterpret_cast<const char*>(q + (size_t)mt * 128 * DD + h * 64);
        #pragma unroll
        for (int i = 0; i < 4; i++) {
            int v = tid + 256 * i;
            int row = v >> 3, c8 = v & 7;
            uint32_t off = (uint32_t)(row * 128 + c8 * 16);
            CP_ASYNC16(sA + SWZ128(off), Ag + (size_t)row * (DD * 2) + c8 * 16);
        }
    }
    const char* Bh = reinterpret_cast<const char*>(wkt + (size_t)h * DD * 64);
    auto load_B = [&](int nt, int buf) {
        uint32_t bbase = sB0 + buf * QF_B;
        const char* Bg = Bh + (size_t)nt * 256 * 128;
        #pragma unroll
        for (int i = 0; i < 8; i++) {
            int v = tid + 256 * i;
            int row = v >> 3, c8 = v & 7;
            uint32_t off = (uint32_t)(row * 128 + c8 * 16);
            CP_ASYNC16(bbase + SWZ128(off), Bg + (size_t)row * 128 + c8 * 16);
        }
    };
    load_B(0, 0);
    CP_COMMIT();            // group: A + B0
    load_B(1, 1);
    CP_COMMIT();            // group: B1

    for (int nt = 0; nt < 4; nt++) {
        if (nt >= 1 && nt + 1 < 4) {
            load_B(nt + 1, (nt + 1) & 1);
            CP_COMMIT();
        }
        if (nt < 3) asm volatile("cp.async.wait_group 1;" ::: "memory");
        else        asm volatile("cp.async.wait_group 0;" ::: "memory");
        __syncthreads();

        uint32_t bbase = sB0 + (nt & 1) * QF_B;
        float acc[4][8][4];
        #pragma unroll
        for (int i = 0; i < 4; i++)
            #pragma unroll
            for (int j = 0; j < 8; j++)
                #pragma unroll
                for (int r = 0; r < 4; r++) acc[i][j][r] = 0.f;

        #pragma unroll
        for (int k16 = 0; k16 < 4; k16++) {
            uint32_t af[4][4];
            #pragma unroll
            for (int i = 0; i < 4; i++) {
                int row = wm * 64 + i * 16 + (lane & 15);
                uint32_t off = (uint32_t)(row * 128 + k16 * 32 + (lane >> 4) * 16);
                ldmatrix_x4(af[i], sA + SWZ128(off));
            }
            uint32_t bfr[4][4];
            #pragma unroll
            for (int j2 = 0; j2 < 4; j2++) {
                int nrow = wn * 64 + j2 * 16 + (lane & 7) + ((lane >> 4) << 3);
                uint32_t off = (uint32_t)(nrow * 128 + k16 * 32 + ((lane >> 3) & 1) * 16);
                ldmatrix_x4(bfr[j2], bbase + SWZ128(off));
            }
            #pragma unroll
            for (int i = 0; i < 4; i++)
                #pragma unroll
                for (int j = 0; j < 8; j++)
                    mma16816(acc[i][j], af[i], bfr[j >> 1][(j & 1) * 2], bfr[j >> 1][(j & 1) * 2 + 1]);
        }

        // pack + conflict-free STS into staging (row stride 528B: 132 words, 132%32=4)
        #pragma unroll
        for (int i = 0; i < 4; i++) {
            #pragma unroll
            for (int half = 0; half < 2; half++) {
                int row = wm * 64 + i * 16 + half * 8 + (lane >> 2);
                uint32_t rb = sOut + (uint32_t)row * 528 + (uint32_t)(wn * 64 + (lane & 3) * 2) * 2;
                #pragma unroll
                for (int j = 0; j < 8; j++) {
                    uint32_t p = pack_bf16(acc[i][j][half * 2 + 0], acc[i][j][half * 2 + 1]);
                    asm volatile("st.shared.b32 [%0], %1;" :: "r"(rb + j * 16), "r"(p));
                }
            }
        }
        __syncthreads();

        // coalesced copy-out: 128 rows x 512B; head-major layout -> row stride DD (2KB)
        {
            size_t gbase = ((size_t)h * MQ + (size_t)mt * 128) * DD + nt * 256;
            #pragma unroll
            for (int it = 0; it < 16; it++) {
                int idx = tid + 256 * it;
                int row = idx >> 5, c = idx & 31;
                uint4 v;
                asm volatile("ld.shared.v4.b32 {%0,%1,%2,%3}, [%4];"
                             : "=r"(v.x), "=r"(v.y), "=r"(v.z), "=r"(v.w)
                             : "r"(sOut + (uint32_t)row * 528 + (uint32_t)c * 16));
                *reinterpret_cast<uint4*>(qk + gbase + (size_t)row * DD + c * 8) = v;
            }
        }
        __syncthreads();   // staging + B buffer reuse barrier
    }
}

// ---------------- fused attention: smem qk + bf16 hist, 4-warp split-K logits ----------------
#define ATT_PAD 2064
static constexpr int ATT_QK = HH * ATT_PAD;            // 33024
static constexpr int ATT_HIST = NP * ATT_PAD;          // 16512
static constexpr int ATT_PLOG_OFF = ATT_QK + ATT_HIST; // 49536
static constexpr int ATT_AS_OFF = ATT_PLOG_OFF + 4 * HH * NP * 4;  // 51584
static constexpr int ATT_SMEM = ATT_AS_OFF + HH * NP * 4;          // 52096

__global__ void __launch_bounds__(128) attn_fused2(
    const float* __restrict__ hist,          // [8192][8][1024] fp32
    const __nv_bfloat16* __restrict__ qk,    // [16][8192][1024]
    __nv_bfloat16* __restrict__ hm,          // [16][8192][1024]
    int bs0)
{
    extern __shared__ char sm[];
    char* qk_s = sm;
    char* hist_s = sm + ATT_QK;
    float* plog = reinterpret_cast<float*>(sm + ATT_PLOG_OFF);  // [4][16][8]
    float* a_s = reinterpret_cast<float*>(sm + ATT_AS_OFF);     // [16][8]
    int bs = blockIdx.x + bs0;
    int tid = threadIdx.x, lane = tid & 31, w = tid >> 5;

    // stage qk: per head hh, row qk[hh][bs][0..1024) (2KB contiguous)
    {
        #pragma unroll
        for (int i = 0; i < 16; i++) {
            int idx = tid + 128 * i;
            int hh = idx >> 7, c = idx & 127;
            uint4 v = *reinterpret_cast<const uint4*>(qk + ((size_t)hh * MQ + bs) * DD + c * 8);
            *reinterpret_cast<uint4*>(qk_s + hh * ATT_PAD + c * 16) = v;
        }
    }
    // stage hist fp32 -> bf16
    {
        const float4* hg = reinterpret_cast<const float4*>(hist + (size_t)bs * (NP * DD));
        #pragma unroll
        for (int i = 0; i < 16; i++) {
            int idx = tid + 128 * i;
            int n = idx >> 8, c = idx & 255;
            float4 f = hg[idx];
            uint2 p;
            p.x = pack_bf16(f.x, f.y);
            p.y = pack_bf16(f.z, f.w);
            *reinterpret_cast<uint2*>(hist_s + n * ATT_PAD + c * 8) = p;
        }
    }
    __syncthreads();

    // logits: warp w covers k = [w*256, w*256+256), 16 k16-steps
    {
        float c4[4] = {0.f, 0.f, 0.f, 0.f};
        int arow = lane & 15, akoff = (lane >> 4) * 8;
        int brow = lane & 7, bkoff = ((lane >> 3) & 1) * 8;
        #pragma unroll
        for (int kk = 0; kk < 16; kk++) {
            int k0 = w * 256 + kk * 16;
            uint32_t a[4];
            ldmatrix_x4(a, smem_u32(qk_s + arow * ATT_PAD + (k0 + akoff) * 2));
            uint32_t b0, b1;
            ldmatrix_x2(b0, b1, smem_u32(hist_s + brow * ATT_PAD + (k0 + bkoff) * 2));
            mma16816(c4, a, b0, b1);
        }
        int r = lane >> 2, cq = (lane & 3) * 2;
        plog[w * 128 + r * 8 + cq] = c4[0];
        plog[w * 128 + r * 8 + cq + 1] = c4[1];
        plog[w * 128 + (r + 8) * 8 + cq] = c4[2];
        plog[w * 128 + (r + 8) * 8 + cq + 1] = c4[3];
    }
    __syncthreads();

    if (w == 0) {
        int r = lane >> 2, cq = (lane & 3) * 2;
        float c0 = 0.f, c1 = 0.f, c2 = 0.f, c3 = 0.f;
        #pragma unroll
        for (int ww = 0; ww < 4; ww++) {
            c0 += plog[ww * 128 + r * 8 + cq];
            c1 += plog[ww * 128 + r * 8 + cq + 1];
            c2 += plog[ww * 128 + (r + 8) * 8 + cq];
            c3 += plog[ww * 128 + (r + 8) * 8 + cq + 1];
        }
        const float scale = 0.125f;
        c0 *= scale; c1 *= scale; c2 *= scale; c3 *= scale;
        float m01 = fmaxf(c0, c1), m23 = fmaxf(c2, c3);
        #pragma unroll
        for (int o = 1; o <= 2; o <<= 1) {
            m01 = fmaxf(m01, __shfl_xor_sync(0xffffffffu, m01, o));
            m23 = fmaxf(m23, __shfl_xor_sync(0xffffffffu, m23, o));
        }
        float e0 = __expf(c0 - m01), e1 = __expf(c1 - m01);
        float e2 = __expf(c2 - m23), e3 = __expf(c3 - m23);
        float s01 = e0 + e1, s23 = e2 + e3;
        #pragma unroll
        for (int o = 1; o <= 2; o <<= 1) {
            s01 += __shfl_xor_sync(0xffffffffu, s01, o);
            s23 += __shfl_xor_sync(0xffffffffu, s23, o);
        }
        float i01 = __frcp_rn(s01), i23 = __frcp_rn(s23);
        a_s[r * 8 + cq] = e0 * i01;       a_s[r * 8 + cq + 1] = e1 * i01;
        a_s[(r + 8) * 8 + cq] = e2 * i23; a_s[(r + 8) * 8 + cq + 1] = e3 * i23;
    }
    __syncthreads();

    // hm: warp w -> heads 4w..4w+3; head-major output rows (2KB contiguous per head)
    float aw[4][NP];
    #pragma unroll
    for (int hh = 0; hh < 4; hh++)
        #pragma unroll
        for (int n = 0; n < NP; n++) aw[hh][n] = a_s[(w * 4 + hh) * 8 + n];
    #pragma unroll 2
    for (int dc = 0; dc < 16; dc++) {
        int d0 = dc * 64 + 2 * lane;
        float2 hv[NP];
        #pragma unroll
        for (int n = 0; n < NP; n++)
            hv[n] = bf2_to_f2(*reinterpret_cast<const uint32_t*>(hist_s + n * ATT_PAD + d0 * 2));
        #pragma unroll
        for (int hh = 0; hh < 4; hh++) {
            float ax = 0.f, ay = 0.f;
            #pragma unroll
            for (int n = 0; n < NP; n++) {
                ax += aw[hh][n] * hv[n].x;
                ay += aw[hh][n] * hv[n].y;
            }
            *reinterpret_cast<uint32_t*>(hm + ((size_t)(w * 4 + hh) * MQ + bs) * DD + d0) =
                pack_bf16(ax, ay);
        }
    }
}

// ---------------- vm: ao[bs][h*64+j] = sum_d hm[h][bs][d] * Wv[h*64+j][d] ----------------
static constexpr int VA_BYTES = 128 * 128;
static constexpr int VB_BYTES = 64 * 128;
static constexpr int VSTAGE_BYTES = VA_BYTES + VB_BYTES;  // 24KB
static constexpr int VM_SMEM = NSTAGE * VSTAGE_BYTES;     // 96KB

DEV_INLINE void vm_load_stage(uint32_t sb, int buf,
                              const __nv_bfloat16* __restrict__ hmA,
                              const __nv_bfloat16* __restrict__ Bg,
                              int k0, int tid) {
    uint32_t abase = sb + buf * VSTAGE_BYTES;
    uint32_t bbase = abase + VA_BYTES;
    const char* Ag = reinterpret_cast<const char*>(hmA + k0);
    const char* Bc = reinterpret_cast<const char*>(Bg + k0);
    #pragma unroll
    for (int i = 0; i < 8; i++) {     // A rows now contiguous at DD stride (head-major hm)
        int v = tid + 128 * i;
        int row = v >> 3, c8 = v & 7;
        uint32_t off = (uint32_t)(row * 128 + c8 * 16);
        CP_ASYNC16(abase + SWZ128(off), Ag + (size_t)row * (DD * 2) + c8 * 16);
    }
    #pragma unroll
    for (int i = 0; i < 4; i++) {
        int v = tid + 128 * i;
        int row = v >> 3, c8 = v & 7;
        uint32_t off = (uint32_t)(row * 128 + c8 * 16);
        CP_ASYNC16(bbase + SWZ128(off), Bc + (size_t)row * (DD * 2) + c8 * 16);
    }
}

__global__ void __launch_bounds__(128, 1) vm_gemm(
    const __nv_bfloat16* __restrict__ hm,   // [16][8192][1024]
    const __nv_bfloat16* __restrict__ wv,
    __nv_bfloat16* __restrict__ ao,
    int mt0)
{
    extern __shared__ char smem[];
    uint32_t sb = smem_u32(smem);
    int tid = threadIdx.x;
    int lane = tid & 31, wid = tid >> 5;
    int wm = wid & 1, wn = wid >> 1;
    int mt = blockIdx.x + mt0, h = blockIdx.y;

    const __nv_bfloat16* hmA = hm + ((size_t)h * MQ + (size_t)mt * 128) * DD;
    const __nv_bfloat16* Bg = wv + (size_t)h * 64 * DD;

    float acc[4][4][4];
    #pragma unroll
    for (int i = 0; i < 4; i++)
        #pragma unroll
        for (int j = 0; j < 4; j++)
            #pragma unroll
            for (int r = 0; r < 4; r++) acc[i][j][r] = 0.f;

    #pragma unroll
    for (int s = 0; s < NSTAGE - 1; s++) {
        vm_load_stage(sb, s, hmA, Bg, s * KC, tid);
        CP_COMMIT();
    }

    for (int s = 0; s < KSTAGES; s++) {
        if (s <= KSTAGES - 3)      asm volatile("cp.async.wait_group 2;" ::: "memory");
        else if (s == KSTAGES - 2) asm volatile("cp.async.wait_group 1;" ::: "memory");
        else                       asm volatile("cp.async.wait_group 0;" ::: "memory");
        __syncthreads();

        if (s + NSTAGE - 1 < KSTAGES) {
            vm_load_stage(sb, (s + NSTAGE - 1) & (NSTAGE - 1), hmA, Bg,
                          (s + NSTAGE - 1) * KC, tid);
            CP_COMMIT();
        }

        int buf = s & (NSTAGE - 1);
        uint32_t abase = sb + buf * VSTAGE_BYTES;
        uint32_t bbase = abase + VA_BYTES;
        #pragma unroll
        for (int k16 = 0; k16 < 4; k16++) {
            uint32_t af[4][4];
            #pragma unroll
            for (int i = 0; i < 4; i++) {
                int row = wm * 64 + i * 16 + (lane & 15);
                uint32_t off = (uint32_t)(row * 128 + k16 * 32 + (lane >> 4) * 16);
                ldmatrix_x4(af[i], abase + SWZ128(off));
            }
            uint32_t bfr[2][4];
            #pragma unroll
            for (int j2 = 0; j2 < 2; j2++) {
                int nrow = wn * 32 + j2 * 16 + (lane & 7) + ((lane >> 4) << 3);
                uint32_t off = (uint32_t)(nrow * 128 + k16 * 32 + ((lane >> 3) & 1) * 16);
                ldmatrix_x4(bfr[j2], bbase + SWZ128(off));
            }
            #pragma unroll
            for (int i = 0; i < 4; i++)
                #pragma unroll
                for (int j = 0; j < 4; j++)
                    mma16816(acc[i][j], af[i], bfr[j >> 1][(j & 1) * 2], bfr[j >> 1][(j & 1) * 2 + 1]);
        }
        __syncthreads();
    }

    int rbase = mt * 128 + wm * 64 + (lane >> 2);
    int cbase = wn * 32 + (lane & 3) * 2;
    #pragma unroll
    for (int i = 0; i < 4; i++) {
        #pragma unroll
        for (int half = 0; half < 2; half++) {
            int row = rbase + i * 16 + half * 8;
            size_t base = (size_t)row * DD + h * 64 + cbase;
            #pragma unroll
            for (int j = 0; j < 4; j++) {
                uint32_t p = pack_bf16(acc[i][j][half * 2 + 0], acc[i][j][half * 2 + 1]);
                *reinterpret_cast<uint32_t*>(ao + base + j * 8) = p;
            }
        }
    }
}

// ---------------- launch ----------------
extern "C" void kernel_launch(void* const* d_in, const int* in_sizes, int n_in,
                              void* d_out, int out_size) {
    const float* cur  = (const float*)d_in[0];
    const float* hist = (const float*)d_in[1];
    const float* Wq   = (const float*)d_in[2];
    const float* Wk   = (const float*)d_in[3];
    const float* Wv   = (const float*)d_in[4];
    const float* Wo   = (const float*)d_in[5];
    float* out = (float*)d_out;

    __nv_bfloat16 *p_cur, *p_wq, *p_wkt, *p_wv, *p_wo, *p_q, *p_qk, *p_hm, *p_ao;
    cudaGetSymbolAddress((void**)&p_cur, g_cur);
    cudaGetSymbolAddress((void**)&p_wq, g_wq);
    cudaGetSymbolAddress((void**)&p_wkt, g_wkt);
    cudaGetSymbolAddress((void**)&p_wv, g_wv);
    cudaGetSymbolAddress((void**)&p_wo, g_wo);
    cudaGetSymbolAddress((void**)&p_q, g_q);
    cudaGetSymbolAddress((void**)&p_qk, g_qk);
    cudaGetSymbolAddress((void**)&p_hm, g_hm);
    cudaGetSymbolAddress((void**)&p_ao, g_ao);

    cudaFuncSetAttribute(gemm_hmma<false>, cudaFuncAttributeMaxDynamicSharedMemorySize, GEMM_SMEM);
    cudaFuncSetAttribute(gemm_hmma<true>,  cudaFuncAttributeMaxDynamicSharedMemorySize, GEMM_SMEM);
    cudaFuncSetAttribute(qk_fold2, cudaFuncAttributeMaxDynamicSharedMemorySize, QF_SMEM);
    cudaFuncSetAttribute(attn_fused2, cudaFuncAttributeMaxDynamicSharedMemorySize, ATT_SMEM);
    cudaFuncSetAttribute(vm_gemm, cudaFuncAttributeMaxDynamicSharedMemorySize, VM_SMEM);

    // conversions (one kernel) + Wk transpose
    {
        int nchunks = CUR_CHUNKS + 3 * W_CHUNKS;
        cvt_all<<<(nchunks + 255) / 256, 256>>>(cur, Wq, Wv, Wo, p_cur, p_wq, p_wv, p_wo);
        transp_wk<<<256, 256>>>(Wk, p_wkt);
    }

    // Q = cur @ Wq^T
    gemm_hmma<false><<<(MQ / TM) * 4, 256, GEMM_SMEM>>>(p_cur, p_wq, p_q, nullptr, nullptr);

    // chunked middle pipeline: qk(c) -> attn(c) -> vm(c), 4 chunks of 2048 bs
    // keeps each 64MB qk/hm chunk L2-resident for its consumer
    static constexpr int NCHUNK = 4;
    static constexpr int BS_PER = MQ / NCHUNK;            // 2048
    for (int c = 0; c < NCHUNK; c++) {
        dim3 gq(BS_PER / 128, HH);
        qk_fold2<<<gq, 256, QF_SMEM>>>(p_q, p_wkt, p_qk, c * (BS_PER / 128));
        attn_fused2<<<BS_PER, 128, ATT_SMEM>>>(hist, p_qk, p_hm, c * BS_PER);
        dim3 gv(BS_PER / 128, HH);
        vm_gemm<<<gv, 128, VM_SMEM>>>(p_hm, p_wv, p_ao, c * (BS_PER / 128));
    }

    // out = cur + ao @ Wo^T
    gemm_hmma<true><<<(MQ / TM) * 4, 256, GEMM_SMEM>>>(p_ao, p_wo, nullptr, out, cur);
}

// round 14
// speedup vs baseline: 1.0667x; 1.0667x over previous
#include <cuda_runtime.h>
#include <cuda_bf16.h>
#include <cstdint>

#define DEV_INLINE __device__ __forceinline__

// ---------------- problem sizes ----------------
#define BB   4
#define SSZ  2048
#define NP   8
#define DD   1024
#define HH   16
#define HDIM 64
#define MQ   (BB*SSZ)       // 8192 rows (current)

// ---------------- scratch (device globals; no allocs allowed) ----------------
__device__ __align__(256) __nv_bfloat16 g_cur [(size_t)MQ * DD];
__device__ __align__(256) __nv_bfloat16 g_wq  [(size_t)DD * DD];
__device__ __align__(256) __nv_bfloat16 g_wkt [(size_t)DD * DD];   // [h][i=1024][j=64]
__device__ __align__(256) __nv_bfloat16 g_wv  [(size_t)DD * DD];
__device__ __align__(256) __nv_bfloat16 g_wo  [(size_t)DD * DD];
__device__ __align__(256) __nv_bfloat16 g_q   [(size_t)MQ * DD];
__device__ __align__(256) __nv_bfloat16 g_qk  [(size_t)HH * MQ * DD];  // [h][bs][i] 256MB
__device__ __align__(256) __nv_bfloat16 g_hm  [(size_t)HH * MQ * DD];  // [h][bs][d] 256MB
__device__ __align__(256) __nv_bfloat16 g_ao  [(size_t)MQ * DD];

// ---------------- helpers ----------------
DEV_INLINE uint32_t smem_u32(const void* p) {
    uint32_t a;
    asm("{ .reg .u64 t; cvta.to.shared.u64 t, %1; cvt.u32.u64 %0, t; }" : "=r"(a) : "l"(p));
    return a;
}
#define CP_ASYNC16(sa, g) \
    asm volatile("cp.async.cg.shared.global [%0], [%1], 16;" :: "r"(sa), "l"(g))
#define CP_COMMIT() asm volatile("cp.async.commit_group;" ::: "memory")
#define SWZ128(x) ((x) ^ (((x) >> 3) & 0x70))

DEV_INLINE void ldmatrix_x4(uint32_t* r, uint32_t addr) {
    asm volatile("ldmatrix.sync.aligned.m8n8.x4.shared.b16 {%0,%1,%2,%3}, [%4];"
                 : "=r"(r[0]), "=r"(r[1]), "=r"(r[2]), "=r"(r[3]) : "r"(addr));
}
DEV_INLINE void ldmatrix_x2(uint32_t& r0, uint32_t& r1, uint32_t addr) {
    asm volatile("ldmatrix.sync.aligned.m8n8.x2.shared.b16 {%0,%1}, [%2];"
                 : "=r"(r0), "=r"(r1) : "r"(addr));
}
DEV_INLINE void mma16816(float* c, const uint32_t* a, uint32_t b0, uint32_t b1) {
    asm volatile("mma.sync.aligned.m16n8k16.row.col.f32.bf16.bf16.f32 "
                 "{%0,%1,%2,%3}, {%4,%5,%6,%7}, {%8,%9}, {%0,%1,%2,%3};"
                 : "+f"(c[0]), "+f"(c[1]), "+f"(c[2]), "+f"(c[3])
                 : "r"(a[0]), "r"(a[1]), "r"(a[2]), "r"(a[3]), "r"(b0), "r"(b1));
}
DEV_INLINE uint32_t pack_bf16(float lo, float hi) {
    uint32_t r;
    asm("cvt.rn.bf16x2.f32 %0, %1, %2;" : "=r"(r) : "f"(hi), "f"(lo));
    return r;
}
DEV_INLINE float2 bf2_to_f2(uint32_t u) {
    __nv_bfloat162 h = *reinterpret_cast<__nv_bfloat162*>(&u);
    return make_float2(__bfloat162float(h.x), __bfloat162float(h.y));
}

// ---------------- merged fp32 -> bf16 conversion (cur + Wq + Wv + Wo) ----------------
#define CUR_CHUNKS (MQ * DD / 4)        // 2097152
#define W_CHUNKS   (DD * DD / 4)        // 262144
__global__ void cvt_all(const float* __restrict__ cur, const float* __restrict__ wq,
                        const float* __restrict__ wv, const float* __restrict__ wo,
                        __nv_bfloat16* __restrict__ ocur, __nv_bfloat16* __restrict__ owq,
                        __nv_bfloat16* __restrict__ owv, __nv_bfloat16* __restrict__ owo) {
    int i = blockIdx.x * blockDim.x + threadIdx.x;
    const float* src;
    __nv_bfloat16* dst;
    int off;
    if (i < CUR_CHUNKS) { src = cur; dst = ocur; off = i; }
    else {
        int j = i - CUR_CHUNKS;
        int wsel = j >> 18;
        off = j & (W_CHUNKS - 1);
        src = (wsel == 0) ? wq : (wsel == 1) ? wv : wo;
        dst = (wsel == 0) ? owq : (wsel == 1) ? owv : owo;
    }
    float4 f = reinterpret_cast<const float4*>(src)[off];
    uint2 p;
    p.x = pack_bf16(f.x, f.y);
    p.y = pack_bf16(f.z, f.w);
    reinterpret_cast<uint2*>(dst)[off] = p;
}

// ---------------- Wk transpose: wkt[h][i][j] = Wk[h*64+j][i] ----------------
__global__ void __launch_bounds__(256) transp_wk(const float* __restrict__ wk,
                                                 __nv_bfloat16* __restrict__ wkt) {
    __shared__ float ts[64][65];
    int h = blockIdx.x & 15, ib = blockIdx.x >> 4;
    int tid = threadIdx.x;
    #pragma unroll
    for (int r = 0; r < 16; r++) {
        int idx = tid + 256 * r;
        int j = idx >> 6, il = idx & 63;
        ts[j][il] = wk[(size_t)(h * 64 + j) * DD + ib * 64 + il];
    }
    __syncthreads();
    #pragma unroll
    for (int r = 0; r < 16; r++) {
        int idx = tid + 256 * r;
        int il = idx >> 6, j = idx & 63;
        wkt[((size_t)h * DD + ib * 64 + il) * 64 + j] = __float2bfloat16(ts[j][il]);
    }
}

// ---------------- main HMMA GEMM (128x256, KC=64, 4-stage) ----------------
static constexpr int TM = 128, TN = 256, KC = 64, KSTAGES = DD / KC;  // 16
static constexpr int A_BYTES = 128 * 128;
static constexpr int B_BYTES = 256 * 128;
static constexpr int STAGE_BYTES = A_BYTES + B_BYTES;  // 48 KB
static constexpr int NSTAGE = 4;
static constexpr int GEMM_SMEM = NSTAGE * STAGE_BYTES;  // 192 KB

DEV_INLINE void load_stage(uint32_t sb, int buf,
                           const __nv_bfloat16* __restrict__ A,
                           const __nv_bfloat16* __restrict__ W,
                           int mt, int ntW, int k0, int tid) {
    uint32_t abase = sb + buf * STAGE_BYTES;
    uint32_t bbase = abase + A_BYTES;
    const char* Ag = reinterpret_cast<const char*>(A + (size_t)mt * TM * DD + k0);
    const char* Bg = reinterpret_cast<const char*>(W + (size_t)ntW * TN * DD + k0);
    #pragma unroll
    for (int i = 0; i < 4; i++) {
        int v = tid + 256 * i;
        int row = v >> 3, c8 = v & 7;
        uint32_t off = (uint32_t)(row * 128 + c8 * 16);
        CP_ASYNC16(abase + SWZ128(off), Ag + (size_t)row * (DD * 2) + c8 * 16);
    }
    #pragma unroll
    for (int i = 0; i < 8; i++) {
        int v = tid + 256 * i;
        int row = v >> 3, c8 = v & 7;
        uint32_t off = (uint32_t)(row * 128 + c8 * 16);
        CP_ASYNC16(bbase + SWZ128(off), Bg + (size_t)row * (DD * 2) + c8 * 16);
    }
}

template <bool OUT_F32>
__global__ void __launch_bounds__(256, 1)
gemm_hmma(const __nv_bfloat16* __restrict__ A, const __nv_bfloat16* __restrict__ W,
          __nv_bfloat16* __restrict__ Cb, float* __restrict__ Cf,
          const float* __restrict__ resid) {
    extern __shared__ char smem[];
    uint32_t sb = smem_u32(smem);
    int tid = threadIdx.x;
    int lane = tid & 31, wid = tid >> 5;
    int wm = wid & 1, wn = wid >> 1;
    int ntW = blockIdx.x & 3;
    int mt = blockIdx.x >> 2;

    float acc[4][8][4];
    #pragma unroll
    for (int i = 0; i < 4; i++)
        #pragma unroll
        for (int j = 0; j < 8; j++)
            #pragma unroll
            for (int r = 0; r < 4; r++) acc[i][j][r] = 0.f;

    #pragma unroll
    for (int s = 0; s < NSTAGE - 1; s++) {
        load_stage(sb, s, A, W, mt, ntW, s * KC, tid);
        CP_COMMIT();
    }

    for (int s = 0; s < KSTAGES; s++) {
        if (s <= KSTAGES - 3)      asm volatile("cp.async.wait_group 2;" ::: "memory");
        else if (s == KSTAGES - 2) asm volatile("cp.async.wait_group 1;" ::: "memory");
        else                       asm volatile("cp.async.wait_group 0;" ::: "memory");
        __syncthreads();

        if (s + NSTAGE - 1 < KSTAGES) {
            load_stage(sb, (s + NSTAGE - 1) & (NSTAGE - 1), A, W, mt, ntW,
                       (s + NSTAGE - 1) * KC, tid);
            CP_COMMIT();
        }

        int buf = s & (NSTAGE - 1);
        uint32_t abase = sb + buf * STAGE_BYTES;
        uint32_t bbase = abase + A_BYTES;
        #pragma unroll
        for (int k16 = 0; k16 < 4; k16++) {
            uint32_t af[4][4];
            #pragma unroll
            for (int i = 0; i < 4; i++) {
                int row = wm * 64 + i * 16 + (lane & 15);
                uint32_t off = (uint32_t)(row * 128 + k16 * 32 + (lane >> 4) * 16);
                ldmatrix_x4(af[i], abase + SWZ128(off));
            }
            uint32_t bfr[4][4];
            #pragma unroll
            for (int j2 = 0; j2 < 4; j2++) {
                int nrow = wn * 64 + j2 * 16 + (lane & 7) + ((lane >> 4) << 3);
                uint32_t off = (uint32_t)(nrow * 128 + k16 * 32 + ((lane >> 3) & 1) * 16);
                ldmatrix_x4(bfr[j2], bbase + SWZ128(off));
            }
            #pragma unroll
            for (int i = 0; i < 4; i++)
                #pragma unroll
                for (int j = 0; j < 8; j++)
                    mma16816(acc[i][j], af[i], bfr[j >> 1][(j & 1) * 2], bfr[j >> 1][(j & 1) * 2 + 1]);
        }
        __syncthreads();
    }

    int rbase = mt * TM + wm * 64 + (lane >> 2);
    int cbase = ntW * TN + wn * 64 + (lane & 3) * 2;
    #pragma unroll
    for (int i = 0; i < 4; i++) {
        #pragma unroll
        for (int half = 0; half < 2; half++) {
            int row = rbase + i * 16 + half * 8;
            size_t base = (size_t)row * DD + cbase;
            if (OUT_F32) {
                #pragma unroll
                for (int j = 0; j < 8; j++) {
                    size_t idx = base + j * 8;
                    float2 rs = *reinterpret_cast<const float2*>(resid + idx);
                    float2 o;
                    o.x = acc[i][j][half * 2 + 0] + rs.x;
                    o.y = acc[i][j][half * 2 + 1] + rs.y;
                    *reinterpret_cast<float2*>(Cf + idx) = o;
                }
            } else {
                #pragma unroll
                for (int j = 0; j < 8; j++) {
                    uint32_t p = pack_bf16(acc[i][j][half * 2 + 0], acc[i][j][half * 2 + 1]);
                    *reinterpret_cast<uint32_t*>(Cb + base + j * 8) = p;
                }
            }
        }
    }
}

// ---------------- qk fold (TM=128, head-major output, staged coalesced epilogue) ----------------
// qk[h][bs][i] = sum_j q[bs][h*64+j] * wkt[h][i][j]
static constexpr int QF_A = 128 * 128;              // 16 KB
static constexpr int QF_B = 256 * 128;              // 32 KB
static constexpr int QF_OUT = 128 * 528;            // 67584
static constexpr int QF_SMEM = QF_A + 2 * QF_B + QF_OUT;   // 149504

__global__ void __launch_bounds__(256, 1) qk_fold2(
    const __nv_bfloat16* __restrict__ q,    // [8192][1024]
    const __nv_bfloat16* __restrict__ wkt,  // [16][1024][64]
    __nv_bfloat16* __restrict__ qk)         // [16][8192][1024]
{
    extern __shared__ char smem[];
    uint32_t sA = smem_u32(smem);
    uint32_t sB0 = sA + QF_A;
    uint32_t sOut = sB0 + 2 * QF_B;
    int tid = threadIdx.x;
    int lane = tid & 31, wid = tid >> 5;
    int wm = wid & 1, wn = wid >> 1;       // 2(M) x 4(N)
    int mt = blockIdx.x, h = blockIdx.y;

    {
        const char* Ag = reinterpret_cast<const char*>(q + (size_t)mt * 128 * DD + h * 64);
        #pragma unroll
        for (int i = 0; i < 4; i++) {
            int v = tid + 256 * i;
            int row = v >> 3, c8 = v & 7;
            uint32_t off = (uint32_t)(row * 128 + c8 * 16);
            CP_ASYNC16(sA + SWZ128(off), Ag + (size_t)row * (DD * 2) + c8 * 16);
        }
    }
    const char* Bh = reinterpret_cast<const char*>(wkt + (size_t)h * DD * 64);
    auto load_B = [&](int nt, int buf) {
        uint32_t bbase = sB0 + buf * QF_B;
        const char* Bg = Bh + (size_t)nt * 256 * 128;
        #pragma unroll
        for (int i = 0; i < 8; i++) {
            int v = tid + 256 * i;
            int row = v >> 3, c8 = v & 7;
            uint32_t off = (uint32_t)(row * 128 + c8 * 16);
            CP_ASYNC16(bbase + SWZ128(off), Bg + (size_t)row * 128 + c8 * 16);
        }
    };
    load_B(0, 0);
    CP_COMMIT();            // group: A + B0
    load_B(1, 1);
    CP_COMMIT();            // group: B1

    for (int nt = 0; nt < 4; nt++) {
        if (nt >= 1 && nt + 1 < 4) {
            load_B(nt + 1, (nt + 1) & 1);
            CP_COMMIT();
        }
        if (nt < 3) asm volatile("cp.async.wait_group 1;" ::: "memory");
        else        asm volatile("cp.async.wait_group 0;" ::: "memory");
        __syncthreads();

        uint32_t bbase = sB0 + (nt & 1) * QF_B;
        float acc[4][8][4];
        #pragma unroll
        for (int i = 0; i < 4; i++)
            #pragma unroll
            for (int j = 0; j < 8; j++)
                #pragma unroll
                for (int r = 0; r < 4; r++) acc[i][j][r] = 0.f;

        #pragma unroll
        for (int k16 = 0; k16 < 4; k16++) {
            uint32_t af[4][4];
            #pragma unroll
            for (int i = 0; i < 4; i++) {
                int row = wm * 64 + i * 16 + (lane & 15);
                uint32_t off = (uint32_t)(row * 128 + k16 * 32 + (lane >> 4) * 16);
                ldmatrix_x4(af[i], sA + SWZ128(off));
            }
            uint32_t bfr[4][4];
            #pragma unroll
            for (int j2 = 0; j2 < 4; j2++) {
                int nrow = wn * 64 + j2 * 16 + (lane & 7) + ((lane >> 4) << 3);
                uint32_t off = (uint32_t)(nrow * 128 + k16 * 32 + ((lane >> 3) & 1) * 16);
                ldmatrix_x4(bfr[j2], bbase + SWZ128(off));
            }
            #pragma unroll
            for (int i = 0; i < 4; i++)
                #pragma unroll
                for (int j = 0; j < 8; j++)
                    mma16816(acc[i][j], af[i], bfr[j >> 1][(j & 1) * 2], bfr[j >> 1][(j & 1) * 2 + 1]);
        }

        // pack + conflict-free STS into staging (row stride 528B: 132 words, 132%32=4)
        #pragma unroll
        for (int i = 0; i < 4; i++) {
            #pragma unroll
            for (int half = 0; half < 2; half++) {
                int row = wm * 64 + i * 16 + half * 8 + (lane >> 2);
                uint32_t rb = sOut + (uint32_t)row * 528 + (uint32_t)(wn * 64 + (lane & 3) * 2) * 2;
                #pragma unroll
                for (int j = 0; j < 8; j++) {
                    uint32_t p = pack_bf16(acc[i][j][half * 2 + 0], acc[i][j][half * 2 + 1]);
                    asm volatile("st.shared.b32 [%0], %1;" :: "r"(rb + j * 16), "r"(p));
                }
            }
        }
        __syncthreads();

        // coalesced copy-out: 128 rows x 512B; head-major layout -> row stride DD (2KB)
        {
            size_t gbase = ((size_t)h * MQ + (size_t)mt * 128) * DD + nt * 256;
            #pragma unroll
            for (int it = 0; it < 16; it++) {
                int idx = tid + 256 * it;
                int row = idx >> 5, c = idx & 31;
                uint4 v;
                asm volatile("ld.shared.v4.b32 {%0,%1,%2,%3}, [%4];"
                             : "=r"(v.x), "=r"(v.y), "=r"(v.z), "=r"(v.w)
                             : "r"(sOut + (uint32_t)row * 528 + (uint32_t)c * 16));
                *reinterpret_cast<uint4*>(qk + gbase + (size_t)row * DD + c * 8) = v;
            }
        }
        __syncthreads();   // staging + B buffer reuse barrier
    }
}

// ---------------- fused attention: smem qk + bf16 hist, 4-warp split-K logits ----------------
#define ATT_PAD 2064
static constexpr int ATT_QK = HH * ATT_PAD;            // 33024
static constexpr int ATT_HIST = NP * ATT_PAD;          // 16512
static constexpr int ATT_PLOG_OFF = ATT_QK + ATT_HIST; // 49536
static constexpr int ATT_AS_OFF = ATT_PLOG_OFF + 4 * HH * NP * 4;  // 51584
static constexpr int ATT_SMEM = ATT_AS_OFF + HH * NP * 4;          // 52096

__global__ void __launch_bounds__(128) attn_fused2(
    const float* __restrict__ hist,          // [8192][8][1024] fp32
    const __nv_bfloat16* __restrict__ qk,    // [16][8192][1024]
    __nv_bfloat16* __restrict__ hm)          // [16][8192][1024]
{
    extern __shared__ char sm[];
    char* qk_s = sm;
    char* hist_s = sm + ATT_QK;
    float* plog = reinterpret_cast<float*>(sm + ATT_PLOG_OFF);  // [4][16][8]
    float* a_s = reinterpret_cast<float*>(sm + ATT_AS_OFF);     // [16][8]
    int bs = blockIdx.x;
    int tid = threadIdx.x, lane = tid & 31, w = tid >> 5;

    // stage qk: per head hh, row qk[hh][bs][0..1024) (2KB contiguous)
    {
        #pragma unroll
        for (int i = 0; i < 16; i++) {
            int idx = tid + 128 * i;
            int hh = idx >> 7, c = idx & 127;
            uint4 v = *reinterpret_cast<const uint4*>(qk + ((size_t)hh * MQ + bs) * DD + c * 8);
            *reinterpret_cast<uint4*>(qk_s + hh * ATT_PAD + c * 16) = v;
        }
    }
    // stage hist fp32 -> bf16
    {
        const float4* hg = reinterpret_cast<const float4*>(hist + (size_t)bs * (NP * DD));
        #pragma unroll
        for (int i = 0; i < 16; i++) {
            int idx = tid + 128 * i;
            int n = idx >> 8, c = idx & 255;
            float4 f = hg[idx];
            uint2 p;
            p.x = pack_bf16(f.x, f.y);
            p.y = pack_bf16(f.z, f.w);
            *reinterpret_cast<uint2*>(hist_s + n * ATT_PAD + c * 8) = p;
        }
    }
    __syncthreads();

    // logits: warp w covers k = [w*256, w*256+256), 16 k16-steps
    {
        float c4[4] = {0.f, 0.f, 0.f, 0.f};
        int arow = lane & 15, akoff = (lane >> 4) * 8;
        int brow = lane & 7, bkoff = ((lane >> 3) & 1) * 8;
        #pragma unroll
        for (int kk = 0; kk < 16; kk++) {
            int k0 = w * 256 + kk * 16;
            uint32_t a[4];
            ldmatrix_x4(a, smem_u32(qk_s + arow * ATT_PAD + (k0 + akoff) * 2));
            uint32_t b0, b1;
            ldmatrix_x2(b0, b1, smem_u32(hist_s + brow * ATT_PAD + (k0 + bkoff) * 2));
            mma16816(c4, a, b0, b1);
        }
        int r = lane >> 2, cq = (lane & 3) * 2;
        plog[w * 128 + r * 8 + cq] = c4[0];
        plog[w * 128 + r * 8 + cq + 1] = c4[1];
        plog[w * 128 + (r + 8) * 8 + cq] = c4[2];
        plog[w * 128 + (r + 8) * 8 + cq + 1] = c4[3];
    }
    __syncthreads();

    if (w == 0) {
        int r = lane >> 2, cq = (lane & 3) * 2;
        float c0 = 0.f, c1 = 0.f, c2 = 0.f, c3 = 0.f;
        #pragma unroll
        for (int ww = 0; ww < 4; ww++) {
            c0 += plog[ww * 128 + r * 8 + cq];
            c1 += plog[ww * 128 + r * 8 + cq + 1];
            c2 += plog[ww * 128 + (r + 8) * 8 + cq];
            c3 += plog[ww * 128 + (r + 8) * 8 + cq + 1];
        }
        const float scale = 0.125f;
        c0 *= scale; c1 *= scale; c2 *= scale; c3 *= scale;
        float m01 = fmaxf(c0, c1), m23 = fmaxf(c2, c3);
        #pragma unroll
        for (int o = 1; o <= 2; o <<= 1) {
            m01 = fmaxf(m01, __shfl_xor_sync(0xffffffffu, m01, o));
            m23 = fmaxf(m23, __shfl_xor_sync(0xffffffffu, m23, o));
        }
        float e0 = __expf(c0 - m01), e1 = __expf(c1 - m01);
        float e2 = __expf(c2 - m23), e3 = __expf(c3 - m23);
        float s01 = e0 + e1, s23 = e2 + e3;
        #pragma unroll
        for (int o = 1; o <= 2; o <<= 1) {
            s01 += __shfl_xor_sync(0xffffffffu, s01, o);
            s23 += __shfl_xor_sync(0xffffffffu, s23, o);
        }
        float i01 = __frcp_rn(s01), i23 = __frcp_rn(s23);
        a_s[r * 8 + cq] = e0 * i01;       a_s[r * 8 + cq + 1] = e1 * i01;
        a_s[(r + 8) * 8 + cq] = e2 * i23; a_s[(r + 8) * 8 + cq + 1] = e3 * i23;
    }
    __syncthreads();

    // hm: warp w -> heads 4w..4w+3; head-major output rows (2KB contiguous per head)
    float aw[4][NP];
    #pragma unroll
    for (int hh = 0; hh < 4; hh++)
        #pragma unroll
        for (int n = 0; n < NP; n++) aw[hh][n] = a_s[(w * 4 + hh) * 8 + n];
    #pragma unroll 2
    for (int dc = 0; dc < 16; dc++) {
        int d0 = dc * 64 + 2 * lane;
        float2 hv[NP];
        #pragma unroll
        for (int n = 0; n < NP; n++)
            hv[n] = bf2_to_f2(*reinterpret_cast<const uint32_t*>(hist_s + n * ATT_PAD + d0 * 2));
        #pragma unroll
        for (int hh = 0; hh < 4; hh++) {
            float ax = 0.f, ay = 0.f;
            #pragma unroll
            for (int n = 0; n < NP; n++) {
                ax += aw[hh][n] * hv[n].x;
                ay += aw[hh][n] * hv[n].y;
            }
            *reinterpret_cast<uint32_t*>(hm + ((size_t)(w * 4 + hh) * MQ + bs) * DD + d0) =
                pack_bf16(ax, ay);
        }
    }
}

// ---------------- vm: ao[bs][h*64+j] = sum_d hm[h][bs][d] * Wv[h*64+j][d] ----------------
static constexpr int VA_BYTES = 128 * 128;
static constexpr int VB_BYTES = 64 * 128;
static constexpr int VSTAGE_BYTES = VA_BYTES + VB_BYTES;  // 24KB
static constexpr int VM_SMEM = NSTAGE * VSTAGE_BYTES;     // 96KB

DEV_INLINE void vm_load_stage(uint32_t sb, int buf,
                              const __nv_bfloat16* __restrict__ hmA,
                              const __nv_bfloat16* __restrict__ Bg,
                              int k0, int tid) {
    uint32_t abase = sb + buf * VSTAGE_BYTES;
    uint32_t bbase = abase + VA_BYTES;
    const char* Ag = reinterpret_cast<const char*>(hmA + k0);
    const char* Bc = reinterpret_cast<const char*>(Bg + k0);
    #pragma unroll
    for (int i = 0; i < 8; i++) {     // A rows contiguous at DD stride (head-major hm)
        int v = tid + 128 * i;
        int row = v >> 3, c8 = v & 7;
        uint32_t off = (uint32_t)(row * 128 + c8 * 16);
        CP_ASYNC16(abase + SWZ128(off), Ag + (size_t)row * (DD * 2) + c8 * 16);
    }
    #pragma unroll
    for (int i = 0; i < 4; i++) {
        int v = tid + 128 * i;
        int row = v >> 3, c8 = v & 7;
        uint32_t off = (uint32_t)(row * 128 + c8 * 16);
        CP_ASYNC16(bbase + SWZ128(off), Bc + (size_t)row * (DD * 2) + c8 * 16);
    }
}

__global__ void __launch_bounds__(128, 1) vm_gemm(
    const __nv_bfloat16* __restrict__ hm,   // [16][8192][1024]
    const __nv_bfloat16* __restrict__ wv,
    __nv_bfloat16* __restrict__ ao)
{
    extern __shared__ char smem[];
    uint32_t sb = smem_u32(smem);
    int tid = threadIdx.x;
    int lane = tid & 31, wid = tid >> 5;
    int wm = wid & 1, wn = wid >> 1;
    int mt = blockIdx.x, h = blockIdx.y;

    const __nv_bfloat16* hmA = hm + ((size_t)h * MQ + (size_t)mt * 128) * DD;
    const __nv_bfloat16* Bg = wv + (size_t)h * 64 * DD;

    float acc[4][4][4];
    #pragma unroll
    for (int i = 0; i < 4; i++)
        #pragma unroll
        for (int j = 0; j < 4; j++)
            #pragma unroll
            for (int r = 0; r < 4; r++) acc[i][j][r] = 0.f;

    #pragma unroll
    for (int s = 0; s < NSTAGE - 1; s++) {
        vm_load_stage(sb, s, hmA, Bg, s * KC, tid);
        CP_COMMIT();
    }

    for (int s = 0; s < KSTAGES; s++) {
        if (s <= KSTAGES - 3)      asm volatile("cp.async.wait_group 2;" ::: "memory");
        else if (s == KSTAGES - 2) asm volatile("cp.async.wait_group 1;" ::: "memory");
        else                       asm volatile("cp.async.wait_group 0;" ::: "memory");
        __syncthreads();

        if (s + NSTAGE - 1 < KSTAGES) {
            vm_load_stage(sb, (s + NSTAGE - 1) & (NSTAGE - 1), hmA, Bg,
                          (s + NSTAGE - 1) * KC, tid);
            CP_COMMIT();
        }

        int buf = s & (NSTAGE - 1);
        uint32_t abase = sb + buf * VSTAGE_BYTES;
        uint32_t bbase = abase + VA_BYTES;
        #pragma unroll
        for (int k16 = 0; k16 < 4; k16++) {
            uint32_t af[4][4];
            #pragma unroll
            for (int i = 0; i < 4; i++) {
                int row = wm * 64 + i * 16 + (lane & 15);
                uint32_t off = (uint32_t)(row * 128 + k16 * 32 + (lane >> 4) * 16);
                ldmatrix_x4(af[i], abase + SWZ128(off));
            }
            uint32_t bfr[2][4];
            #pragma unroll
            for (int j2 = 0; j2 < 2; j2++) {
                int nrow = wn * 32 + j2 * 16 + (lane & 7) + ((lane >> 4) << 3);
                uint32_t off = (uint32_t)(nrow * 128 + k16 * 32 + ((lane >> 3) & 1) * 16);
                ldmatrix_x4(bfr[j2], bbase + SWZ128(off));
            }
            #pragma unroll
            for (int i = 0; i < 4; i++)
                #pragma unroll
                for (int j = 0; j < 4; j++)
                    mma16816(acc[i][j], af[i], bfr[j >> 1][(j & 1) * 2], bfr[j >> 1][(j & 1) * 2 + 1]);
        }
        __syncthreads();
    }

    int rbase = mt * 128 + wm * 64 + (lane >> 2);
    int cbase = wn * 32 + (lane & 3) * 2;
    #pragma unroll
    for (int i = 0; i < 4; i++) {
        #pragma unroll
        for (int half = 0; half < 2; half++) {
            int row = rbase + i * 16 + half * 8;
            size_t base = (size_t)row * DD + h * 64 + cbase;
            #pragma unroll
            for (int j = 0; j < 4; j++) {
                uint32_t p = pack_bf16(acc[i][j][half * 2 + 0], acc[i][j][half * 2 + 1]);
                *reinterpret_cast<uint32_t*>(ao + base + j * 8) = p;
            }
        }
    }
}

// ---------------- launch ----------------
extern "C" void kernel_launch(void* const* d_in, const int* in_sizes, int n_in,
                              void* d_out, int out_size) {
    const float* cur  = (const float*)d_in[0];
    const float* hist = (const float*)d_in[1];
    const float* Wq   = (const float*)d_in[2];
    const float* Wk   = (const float*)d_in[3];
    const float* Wv   = (const float*)d_in[4];
    const float* Wo   = (const float*)d_in[5];
    float* out = (float*)d_out;

    __nv_bfloat16 *p_cur, *p_wq, *p_wkt, *p_wv, *p_wo, *p_q, *p_qk, *p_hm, *p_ao;
    cudaGetSymbolAddress((void**)&p_cur, g_cur);
    cudaGetSymbolAddress((void**)&p_wq, g_wq);
    cudaGetSymbolAddress((void**)&p_wkt, g_wkt);
    cudaGetSymbolAddress((void**)&p_wv, g_wv);
    cudaGetSymbolAddress((void**)&p_wo, g_wo);
    cudaGetSymbolAddress((void**)&p_q, g_q);
    cudaGetSymbolAddress((void**)&p_qk, g_qk);
    cudaGetSymbolAddress((void**)&p_hm, g_hm);
    cudaGetSymbolAddress((void**)&p_ao, g_ao);

    cudaFuncSetAttribute(gemm_hmma<false>, cudaFuncAttributeMaxDynamicSharedMemorySize, GEMM_SMEM);
    cudaFuncSetAttribute(gemm_hmma<true>,  cudaFuncAttributeMaxDynamicSharedMemorySize, GEMM_SMEM);
    cudaFuncSetAttribute(qk_fold2, cudaFuncAttributeMaxDynamicSharedMemorySize, QF_SMEM);
    cudaFuncSetAttribute(attn_fused2, cudaFuncAttributeMaxDynamicSharedMemorySize, ATT_SMEM);
    cudaFuncSetAttribute(vm_gemm, cudaFuncAttributeMaxDynamicSharedMemorySize, VM_SMEM);

    // conversions (one kernel) + Wk transpose
    {
        int nchunks = CUR_CHUNKS + 3 * W_CHUNKS;
        cvt_all<<<(nchunks + 255) / 256, 256>>>(cur, Wq, Wv, Wo, p_cur, p_wq, p_wv, p_wo);
        transp_wk<<<256, 256>>>(Wk, p_wkt);
    }

    // Q = cur @ Wq^T
    gemm_hmma<false><<<(MQ / TM) * 4, 256, GEMM_SMEM>>>(p_cur, p_wq, p_q, nullptr, nullptr);

    // qk fold: per-head q_h @ Wk_h (full grid, head-major output)
    {
        dim3 grid(MQ / 128, HH);
        qk_fold2<<<grid, 256, QF_SMEM>>>(p_q, p_wkt, p_qk);
    }

    // fused attention -> hm (head-major)
    attn_fused2<<<MQ, 128, ATT_SMEM>>>(hist, p_qk, p_hm);

    // vm: per-head hm_h @ Wv_h^T -> ao
    {
        dim3 grid(MQ / 128, HH);
        vm_gemm<<<grid, 128, VM_SMEM>>>(p_hm, p_wv, p_ao);
    }

    // out = cur + ao @ Wo^T
    gemm_hmma<true><<<(MQ / TM) * 4, 256, GEMM_SMEM>>>(p_ao, p_wo, nullptr, out, cur);
}

// round 15
// speedup vs baseline: 1.0708x; 1.0038x over previous
#include <cuda_runtime.h>
#include <cuda_bf16.h>
#include <cstdint>

#define DEV_INLINE __device__ __forceinline__

// ---------------- problem sizes ----------------
#define BB   4
#define SSZ  2048
#define NP   8
#define DD   1024
#define HH   16
#define HDIM 64
#define MQ   (BB*SSZ)       // 8192 rows (current)

// ---------------- scratch (device globals; no allocs allowed) ----------------
__device__ __align__(256) __nv_bfloat16 g_cur [(size_t)MQ * DD];
__device__ __align__(256) __nv_bfloat16 g_wq  [(size_t)DD * DD];
__device__ __align__(256) __nv_bfloat16 g_wkt [(size_t)DD * DD];   // [h][i=1024][j=64]
__device__ __align__(256) __nv_bfloat16 g_wv  [(size_t)DD * DD];
__device__ __align__(256) __nv_bfloat16 g_wo  [(size_t)DD * DD];
__device__ __align__(256) __nv_bfloat16 g_q   [(size_t)MQ * DD];
__device__ __align__(256) __nv_bfloat16 g_qk  [(size_t)HH * MQ * DD];  // [h][bs][i] 256MB
__device__ __align__(256) __nv_bfloat16 g_hm  [(size_t)HH * MQ * DD];  // [h][bs][d] 256MB
__device__ __align__(256) __nv_bfloat16 g_ao  [(size_t)MQ * DD];

// ---------------- helpers ----------------
DEV_INLINE uint32_t smem_u32(const void* p) {
    uint32_t a;
    asm("{ .reg .u64 t; cvta.to.shared.u64 t, %1; cvt.u32.u64 %0, t; }" : "=r"(a) : "l"(p));
    return a;
}
#define CP_ASYNC16(sa, g) \
    asm volatile("cp.async.cg.shared.global [%0], [%1], 16;" :: "r"(sa), "l"(g))
#define CP_COMMIT() asm volatile("cp.async.commit_group;" ::: "memory")
#define SWZ128(x) ((x) ^ (((x) >> 3) & 0x70))

DEV_INLINE void ldmatrix_x4(uint32_t* r, uint32_t addr) {
    asm volatile("ldmatrix.sync.aligned.m8n8.x4.shared.b16 {%0,%1,%2,%3}, [%4];"
                 : "=r"(r[0]), "=r"(r[1]), "=r"(r[2]), "=r"(r[3]) : "r"(addr));
}
DEV_INLINE void ldmatrix_x2(uint32_t& r0, uint32_t& r1, uint32_t addr) {
    asm volatile("ldmatrix.sync.aligned.m8n8.x2.shared.b16 {%0,%1}, [%2];"
                 : "=r"(r0), "=r"(r1) : "r"(addr));
}
DEV_INLINE void mma16816(float* c, const uint32_t* a, uint32_t b0, uint32_t b1) {
    asm volatile("mma.sync.aligned.m16n8k16.row.col.f32.bf16.bf16.f32 "
                 "{%0,%1,%2,%3}, {%4,%5,%6,%7}, {%8,%9}, {%0,%1,%2,%3};"
                 : "+f"(c[0]), "+f"(c[1]), "+f"(c[2]), "+f"(c[3])
                 : "r"(a[0]), "r"(a[1]), "r"(a[2]), "r"(a[3]), "r"(b0), "r"(b1));
}
DEV_INLINE uint32_t pack_bf16(float lo, float hi) {
    uint32_t r;
    asm("cvt.rn.bf16x2.f32 %0, %1, %2;" : "=r"(r) : "f"(hi), "f"(lo));
    return r;
}
DEV_INLINE float2 bf2_to_f2(uint32_t u) {
    __nv_bfloat162 h = *reinterpret_cast<__nv_bfloat162*>(&u);
    return make_float2(__bfloat162float(h.x), __bfloat162float(h.y));
}

// ---------------- merged fp32 -> bf16 conversion (cur + Wq + Wv + Wo) ----------------
#define CUR_CHUNKS (MQ * DD / 4)        // 2097152
#define W_CHUNKS   (DD * DD / 4)        // 262144
__global__ void cvt_all(const float* __restrict__ cur, const float* __restrict__ wq,
                        const float* __restrict__ wv, const float* __restrict__ wo,
                        __nv_bfloat16* __restrict__ ocur, __nv_bfloat16* __restrict__ owq,
                        __nv_bfloat16* __restrict__ owv, __nv_bfloat16* __restrict__ owo) {
    int i = blockIdx.x * blockDim.x + threadIdx.x;
    const float* src;
    __nv_bfloat16* dst;
    int off;
    if (i < CUR_CHUNKS) { src = cur; dst = ocur; off = i; }
    else {
        int j = i - CUR_CHUNKS;
        int wsel = j >> 18;
        off = j & (W_CHUNKS - 1);
        src = (wsel == 0) ? wq : (wsel == 1) ? wv : wo;
        dst = (wsel == 0) ? owq : (wsel == 1) ? owv : owo;
    }
    float4 f = reinterpret_cast<const float4*>(src)[off];
    uint2 p;
    p.x = pack_bf16(f.x, f.y);
    p.y = pack_bf16(f.z, f.w);
    reinterpret_cast<uint2*>(dst)[off] = p;
}

// ---------------- Wk transpose: wkt[h][i][j] = Wk[h*64+j][i] ----------------
__global__ void __launch_bounds__(256) transp_wk(const float* __restrict__ wk,
                                                 __nv_bfloat16* __restrict__ wkt) {
    __shared__ float ts[64][65];
    int h = blockIdx.x & 15, ib = blockIdx.x >> 4;
    int tid = threadIdx.x;
    #pragma unroll
    for (int r = 0; r < 16; r++) {
        int idx = tid + 256 * r;
        int j = idx >> 6, il = idx & 63;
        ts[j][il] = wk[(size_t)(h * 64 + j) * DD + ib * 64 + il];
    }
    __syncthreads();
    #pragma unroll
    for (int r = 0; r < 16; r++) {
        int idx = tid + 256 * r;
        int il = idx >> 6, j = idx & 63;
        wkt[((size_t)h * DD + ib * 64 + il) * 64 + j] = __float2bfloat16(ts[j][il]);
    }
}

// ---------------- main HMMA GEMM (128x256, KC=64, 4-stage) ----------------
static constexpr int TM = 128, TN = 256, KC = 64, KSTAGES = DD / KC;  // 16
static constexpr int A_BYTES = 128 * 128;
static constexpr int B_BYTES = 256 * 128;
static constexpr int STAGE_BYTES = A_BYTES + B_BYTES;  // 48 KB
static constexpr int NSTAGE = 4;
static constexpr int GEMM_SMEM = NSTAGE * STAGE_BYTES;  // 192 KB

DEV_INLINE void load_stage(uint32_t sb, int buf,
                           const __nv_bfloat16* __restrict__ A,
                           const __nv_bfloat16* __restrict__ W,
                           int mt, int ntW, int k0, int tid) {
    uint32_t abase = sb + buf * STAGE_BYTES;
    uint32_t bbase = abase + A_BYTES;
    const char* Ag = reinterpret_cast<const char*>(A + (size_t)mt * TM * DD + k0);
    const char* Bg = reinterpret_cast<const char*>(W + (size_t)ntW * TN * DD + k0);
    #pragma unroll
    for (int i = 0; i < 4; i++) {
        int v = tid + 256 * i;
        int row = v >> 3, c8 = v & 7;
        uint32_t off = (uint32_t)(row * 128 + c8 * 16);
        CP_ASYNC16(abase + SWZ128(off), Ag + (size_t)row * (DD * 2) + c8 * 16);
    }
    #pragma unroll
    for (int i = 0; i < 8; i++) {
        int v = tid + 256 * i;
        int row = v >> 3, c8 = v & 7;
        uint32_t off = (uint32_t)(row * 128 + c8 * 16);
        CP_ASYNC16(bbase + SWZ128(off), Bg + (size_t)row * (DD * 2) + c8 * 16);
    }
}

template <bool OUT_F32>
__global__ void __launch_bounds__(256, 1)
gemm_hmma(const __nv_bfloat16* __restrict__ A, const __nv_bfloat16* __restrict__ W,
          __nv_bfloat16* __restrict__ Cb, float* __restrict__ Cf,
          const float* __restrict__ resid) {
    extern __shared__ char smem[];
    uint32_t sb = smem_u32(smem);
    int tid = threadIdx.x;
    int lane = tid & 31, wid = tid >> 5;
    int wm = wid & 1, wn = wid >> 1;
    int ntW = blockIdx.x & 3;
    int mt = blockIdx.x >> 2;

    float acc[4][8][4];
    #pragma unroll
    for (int i = 0; i < 4; i++)
        #pragma unroll
        for (int j = 0; j < 8; j++)
            #pragma unroll
            for (int r = 0; r < 4; r++) acc[i][j][r] = 0.f;

    #pragma unroll
    for (int s = 0; s < NSTAGE - 1; s++) {
        load_stage(sb, s, A, W, mt, ntW, s * KC, tid);
        CP_COMMIT();
    }

    for (int s = 0; s < KSTAGES; s++) {
        if (s <= KSTAGES - 3)      asm volatile("cp.async.wait_group 2;" ::: "memory");
        else if (s == KSTAGES - 2) asm volatile("cp.async.wait_group 1;" ::: "memory");
        else                       asm volatile("cp.async.wait_group 0;" ::: "memory");
        __syncthreads();

        if (s + NSTAGE - 1 < KSTAGES) {
            load_stage(sb, (s + NSTAGE - 1) & (NSTAGE - 1), A, W, mt, ntW,
                       (s + NSTAGE - 1) * KC, tid);
            CP_COMMIT();
        }

        int buf = s & (NSTAGE - 1);
        uint32_t abase = sb + buf * STAGE_BYTES;
        uint32_t bbase = abase + A_BYTES;
        #pragma unroll
        for (int k16 = 0; k16 < 4; k16++) {
            uint32_t af[4][4];
            #pragma unroll
            for (int i = 0; i < 4; i++) {
                int row = wm * 64 + i * 16 + (lane & 15);
                uint32_t off = (uint32_t)(row * 128 + k16 * 32 + (lane >> 4) * 16);
                ldmatrix_x4(af[i], abase + SWZ128(off));
            }
            uint32_t bfr[4][4];
            #pragma unroll
            for (int j2 = 0; j2 < 4; j2++) {
                int nrow = wn * 64 + j2 * 16 + (lane & 7) + ((lane >> 4) << 3);
                uint32_t off = (uint32_t)(nrow * 128 + k16 * 32 + ((lane >> 3) & 1) * 16);
                ldmatrix_x4(bfr[j2], bbase + SWZ128(off));
            }
            #pragma unroll
            for (int i = 0; i < 4; i++)
                #pragma unroll
                for (int j = 0; j < 8; j++)
                    mma16816(acc[i][j], af[i], bfr[j >> 1][(j & 1) * 2], bfr[j >> 1][(j & 1) * 2 + 1]);
        }
        __syncthreads();
    }

    int rbase = mt * TM + wm * 64 + (lane >> 2);
    int cbase = ntW * TN + wn * 64 + (lane & 3) * 2;
    #pragma unroll
    for (int i = 0; i < 4; i++) {
        #pragma unroll
        for (int half = 0; half < 2; half++) {
            int row = rbase + i * 16 + half * 8;
            size_t base = (size_t)row * DD + cbase;
            if (OUT_F32) {
                #pragma unroll
                for (int j = 0; j < 8; j++) {
                    size_t idx = base + j * 8;
                    float2 rs = *reinterpret_cast<const float2*>(resid + idx);
                    float2 o;
                    o.x = acc[i][j][half * 2 + 0] + rs.x;
                    o.y = acc[i][j][half * 2 + 1] + rs.y;
                    *reinterpret_cast<float2*>(Cf + idx) = o;
                }
            } else {
                #pragma unroll
                for (int j = 0; j < 8; j++) {
                    uint32_t p = pack_bf16(acc[i][j][half * 2 + 0], acc[i][j][half * 2 + 1]);
                    *reinterpret_cast<uint32_t*>(Cb + base + j * 8) = p;
                }
            }
        }
    }
}

// ---------------- qk fold (TM=128, double-buffered staging, pipelined copy-out) ----------------
// qk[h][bs][i] = sum_j q[bs][h*64+j] * wkt[h][i][j]
static constexpr int QF_A = 128 * 128;              // 16 KB
static constexpr int QF_B = 256 * 128;              // 32 KB
static constexpr int QF_OUT = 128 * 528;            // 67584 (x2 buffers)
static constexpr int QF_SMEM = QF_A + 2 * QF_B + 2 * QF_OUT;   // 217088

__global__ void __launch_bounds__(256, 1) qk_fold2(
    const __nv_bfloat16* __restrict__ q,    // [8192][1024]
    const __nv_bfloat16* __restrict__ wkt,  // [16][1024][64]
    __nv_bfloat16* __restrict__ qk)         // [16][8192][1024]
{
    extern __shared__ char smem[];
    uint32_t sA = smem_u32(smem);
    uint32_t sB0 = sA + QF_A;
    uint32_t sOut0 = sB0 + 2 * QF_B;
    int tid = threadIdx.x;
    int lane = tid & 31, wid = tid >> 5;
    int wm = wid & 1, wn = wid >> 1;       // 2(M) x 4(N)
    int mt = blockIdx.x, h = blockIdx.y;

    {
        const char* Ag = reinterpret_cast<const char*>(q + (size_t)mt * 128 * DD + h * 64);
        #pragma unroll
        for (int i = 0; i < 4; i++) {
            int v = tid + 256 * i;
            int row = v >> 3, c8 = v & 7;
            uint32_t off = (uint32_t)(row * 128 + c8 * 16);
            CP_ASYNC16(sA + SWZ128(off), Ag + (size_t)row * (DD * 2) + c8 * 16);
        }
    }
    const char* Bh = reinterpret_cast<const char*>(wkt + (size_t)h * DD * 64);
    auto load_B = [&](int nt, int buf) {
        uint32_t bbase = sB0 + buf * QF_B;
        const char* Bg = Bh + (size_t)nt * 256 * 128;
        #pragma unroll
        for (int i = 0; i < 8; i++) {
            int v = tid + 256 * i;
            int row = v >> 3, c8 = v & 7;
            uint32_t off = (uint32_t)(row * 128 + c8 * 16);
            CP_ASYNC16(bbase + SWZ128(off), Bg + (size_t)row * 128 + c8 * 16);
        }
    };
    // coalesced copy-out of a finished staging buffer for i-chunk nt_st
    auto copyout = [&](int nt_st, int buf) {
        uint32_t so = sOut0 + buf * QF_OUT;
        size_t gbase = ((size_t)h * MQ + (size_t)mt * 128) * DD + nt_st * 256;
        #pragma unroll
        for (int it = 0; it < 16; it++) {
            int idx = tid + 256 * it;
            int row = idx >> 5, c = idx & 31;
            uint4 v;
            asm volatile("ld.shared.v4.b32 {%0,%1,%2,%3}, [%4];"
                         : "=r"(v.x), "=r"(v.y), "=r"(v.z), "=r"(v.w)
                         : "r"(so + (uint32_t)row * 528 + (uint32_t)c * 16));
            *reinterpret_cast<uint4*>(qk + gbase + (size_t)row * DD + c * 8) = v;
        }
    };

    load_B(0, 0);
    CP_COMMIT();            // group: A + B0
    load_B(1, 1);
    CP_COMMIT();            // group: B1

    for (int nt = 0; nt < 4; nt++) {
        if (nt >= 1 && nt + 1 < 4) {
            load_B(nt + 1, (nt + 1) & 1);
            CP_COMMIT();
        }
        if (nt < 3) asm volatile("cp.async.wait_group 1;" ::: "memory");
        else        asm volatile("cp.async.wait_group 0;" ::: "memory");
        __syncthreads();

        uint32_t bbase = sB0 + (nt & 1) * QF_B;
        float acc[4][8][4];
        #pragma unroll
        for (int i = 0; i < 4; i++)
            #pragma unroll
            for (int j = 0; j < 8; j++)
                #pragma unroll
                for (int r = 0; r < 4; r++) acc[i][j][r] = 0.f;

        #pragma unroll
        for (int k16 = 0; k16 < 4; k16++) {
            uint32_t af[4][4];
            #pragma unroll
            for (int i = 0; i < 4; i++) {
                int row = wm * 64 + i * 16 + (lane & 15);
                uint32_t off = (uint32_t)(row * 128 + k16 * 32 + (lane >> 4) * 16);
                ldmatrix_x4(af[i], sA + SWZ128(off));
            }
            uint32_t bfr[4][4];
            #pragma unroll
            for (int j2 = 0; j2 < 4; j2++) {
                int nrow = wn * 64 + j2 * 16 + (lane & 7) + ((lane >> 4) << 3);
                uint32_t off = (uint32_t)(nrow * 128 + k16 * 32 + ((lane >> 3) & 1) * 16);
                ldmatrix_x4(bfr[j2], bbase + SWZ128(off));
            }
            #pragma unroll
            for (int i = 0; i < 4; i++)
                #pragma unroll
                for (int j = 0; j < 8; j++)
                    mma16816(acc[i][j], af[i], bfr[j >> 1][(j & 1) * 2], bfr[j >> 1][(j & 1) * 2 + 1]);
        }

        // drain previous staging buffer (overlaps with this iteration's MMA/STS issue)
        if (nt > 0) copyout(nt - 1, (nt - 1) & 1);

        // pack + conflict-free STS into staging[nt&1] (row stride 528B)
        {
            uint32_t so = sOut0 + (nt & 1) * QF_OUT;
            #pragma unroll
            for (int i = 0; i < 4; i++) {
                #pragma unroll
                for (int half = 0; half < 2; half++) {
                    int row = wm * 64 + i * 16 + half * 8 + (lane >> 2);
                    uint32_t rb = so + (uint32_t)row * 528 + (uint32_t)(wn * 64 + (lane & 3) * 2) * 2;
                    #pragma unroll
                    for (int j = 0; j < 8; j++) {
                        uint32_t p = pack_bf16(acc[i][j][half * 2 + 0], acc[i][j][half * 2 + 1]);
                        asm volatile("st.shared.b32 [%0], %1;" :: "r"(rb + j * 16), "r"(p));
                    }
                }
            }
        }
        __syncthreads();   // staging[nt&1] visible; prev buffer fully drained before reuse
    }
    // tail: drain staging for nt=3 (buffer 1)
    copyout(3, 1);
}

// ---------------- fused attention: smem qk + bf16 hist, 4-warp split-K logits ----------------
#define ATT_PAD 2064
static constexpr int ATT_QK = HH * ATT_PAD;            // 33024
static constexpr int ATT_HIST = NP * ATT_PAD;          // 16512
static constexpr int ATT_PLOG_OFF = ATT_QK + ATT_HIST; // 49536
static constexpr int ATT_AS_OFF = ATT_PLOG_OFF + 4 * HH * NP * 4;  // 51584
static constexpr int ATT_SMEM = ATT_AS_OFF + HH * NP * 4;          // 52096

__global__ void __launch_bounds__(128) attn_fused2(
    const float* __restrict__ hist,          // [8192][8][1024] fp32
    const __nv_bfloat16* __restrict__ qk,    // [16][8192][1024]
    __nv_bfloat16* __restrict__ hm)          // [16][8192][1024]
{
    extern __shared__ char sm[];
    char* qk_s = sm;
    char* hist_s = sm + ATT_QK;
    float* plog = reinterpret_cast<float*>(sm + ATT_PLOG_OFF);  // [4][16][8]
    float* a_s = reinterpret_cast<float*>(sm + ATT_AS_OFF);     // [16][8]
    int bs = blockIdx.x;
    int tid = threadIdx.x, lane = tid & 31, w = tid >> 5;

    // stage qk: per head hh, row qk[hh][bs][0..1024) (2KB contiguous)
    {
        #pragma unroll
        for (int i = 0; i < 16; i++) {
            int idx = tid + 128 * i;
            int hh = idx >> 7, c = idx & 127;
            uint4 v = *reinterpret_cast<const uint4*>(qk + ((size_t)hh * MQ + bs) * DD + c * 8);
            *reinterpret_cast<uint4*>(qk_s + hh * ATT_PAD + c * 16) = v;
        }
    }
    // stage hist fp32 -> bf16
    {
        const float4* hg = reinterpret_cast<const float4*>(hist + (size_t)bs * (NP * DD));
        #pragma unroll
        for (int i = 0; i < 16; i++) {
            int idx = tid + 128 * i;
            int n = idx >> 8, c = idx & 255;
            float4 f = hg[idx];
            uint2 p;
            p.x = pack_bf16(f.x, f.y);
            p.y = pack_bf16(f.z, f.w);
            *reinterpret_cast<uint2*>(hist_s + n * ATT_PAD + c * 8) = p;
        }
    }
    __syncthreads();

    // logits: warp w covers k = [w*256, w*256+256), 16 k16-steps
    {
        float c4[4] = {0.f, 0.f, 0.f, 0.f};
        int arow = lane & 15, akoff = (lane >> 4) * 8;
        int brow = lane & 7, bkoff = ((lane >> 3) & 1) * 8;
        #pragma unroll
        for (int kk = 0; kk < 16; kk++) {
            int k0 = w * 256 + kk * 16;
            uint32_t a[4];
            ldmatrix_x4(a, smem_u32(qk_s + arow * ATT_PAD + (k0 + akoff) * 2));
            uint32_t b0, b1;
            ldmatrix_x2(b0, b1, smem_u32(hist_s + brow * ATT_PAD + (k0 + bkoff) * 2));
            mma16816(c4, a, b0, b1);
        }
        int r = lane >> 2, cq = (lane & 3) * 2;
        plog[w * 128 + r * 8 + cq] = c4[0];
        plog[w * 128 + r * 8 + cq + 1] = c4[1];
        plog[w * 128 + (r + 8) * 8 + cq] = c4[2];
        plog[w * 128 + (r + 8) * 8 + cq + 1] = c4[3];
    }
    __syncthreads();

    if (w == 0) {
        int r = lane >> 2, cq = (lane & 3) * 2;
        float c0 = 0.f, c1 = 0.f, c2 = 0.f, c3 = 0.f;
        #pragma unroll
        for (int ww = 0; ww < 4; ww++) {
            c0 += plog[ww * 128 + r * 8 + cq];
            c1 += plog[ww * 128 + r * 8 + cq + 1];
            c2 += plog[ww * 128 + (r + 8) * 8 + cq];
            c3 += plog[ww * 128 + (r + 8) * 8 + cq + 1];
        }
        const float scale = 0.125f;
        c0 *= scale; c1 *= scale; c2 *= scale; c3 *= scale;
        float m01 = fmaxf(c0, c1), m23 = fmaxf(c2, c3);
        #pragma unroll
        for (int o = 1; o <= 2; o <<= 1) {
            m01 = fmaxf(m01, __shfl_xor_sync(0xffffffffu, m01, o));
            m23 = fmaxf(m23, __shfl_xor_sync(0xffffffffu, m23, o));
        }
        float e0 = __expf(c0 - m01), e1 = __expf(c1 - m01);
        float e2 = __expf(c2 - m23), e3 = __expf(c3 - m23);
        float s01 = e0 + e1, s23 = e2 + e3;
        #pragma unroll
        for (int o = 1; o <= 2; o <<= 1) {
            s01 += __shfl_xor_sync(0xffffffffu, s01, o);
            s23 += __shfl_xor_sync(0xffffffffu, s23, o);
        }
        float i01 = __frcp_rn(s01), i23 = __frcp_rn(s23);
        a_s[r * 8 + cq] = e0 * i01;       a_s[r * 8 + cq + 1] = e1 * i01;
        a_s[(r + 8) * 8 + cq] = e2 * i23; a_s[(r + 8) * 8 + cq + 1] = e3 * i23;
    }
    __syncthreads();

    // hm: warp w -> heads 4w..4w+3; head-major output rows (2KB contiguous per head)
    float aw[4][NP];
    #pragma unroll
    for (int hh = 0; hh < 4; hh++)
        #pragma unroll
        for (int n = 0; n < NP; n++) aw[hh][n] = a_s[(w * 4 + hh) * 8 + n];
    #pragma unroll 2
    for (int dc = 0; dc < 16; dc++) {
        int d0 = dc * 64 + 2 * lane;
        float2 hv[NP];
        #pragma unroll
        for (int n = 0; n < NP; n++)
            hv[n] = bf2_to_f2(*reinterpret_cast<const uint32_t*>(hist_s + n * ATT_PAD + d0 * 2));
        #pragma unroll
        for (int hh = 0; hh < 4; hh++) {
            float ax = 0.f, ay = 0.f;
            #pragma unroll
            for (int n = 0; n < NP; n++) {
                ax += aw[hh][n] * hv[n].x;
                ay += aw[hh][n] * hv[n].y;
            }
            *reinterpret_cast<uint32_t*>(hm + ((size_t)(w * 4 + hh) * MQ + bs) * DD + d0) =
                pack_bf16(ax, ay);
        }
    }
}

// ---------------- vm: ao[bs][h*64+j] = sum_d hm[h][bs][d] * Wv[h*64+j][d] ----------------
static constexpr int VA_BYTES = 128 * 128;
static constexpr int VB_BYTES = 64 * 128;
static constexpr int VSTAGE_BYTES = VA_BYTES + VB_BYTES;  // 24KB
static constexpr int VM_SMEM = NSTAGE * VSTAGE_BYTES;     // 96KB

DEV_INLINE void vm_load_stage(uint32_t sb, int buf,
                              const __nv_bfloat16* __restrict__ hmA,
                              const __nv_bfloat16* __restrict__ Bg,
                              int k0, int tid) {
    uint32_t abase = sb + buf * VSTAGE_BYTES;
    uint32_t bbase = abase + VA_BYTES;
    const char* Ag = reinterpret_cast<const char*>(hmA + k0);
    const char* Bc = reinterpret_cast<const char*>(Bg + k0);
    #pragma unroll
    for (int i = 0; i < 8; i++) {     // A rows contiguous at DD stride (head-major hm)
        int v = tid + 128 * i;
        int row = v >> 3, c8 = v & 7;
        uint32_t off = (uint32_t)(row * 128 + c8 * 16);
        CP_ASYNC16(abase + SWZ128(off), Ag + (size_t)row * (DD * 2) + c8 * 16);
    }
    #pragma unroll
    for (int i = 0; i < 4; i++) {
        int v = tid + 128 * i;
        int row = v >> 3, c8 = v & 7;
        uint32_t off = (uint32_t)(row * 128 + c8 * 16);
        CP_ASYNC16(bbase + SWZ128(off), Bc + (size_t)row * (DD * 2) + c8 * 16);
    }
}

__global__ void __launch_bounds__(128, 1) vm_gemm(
    const __nv_bfloat16* __restrict__ hm,   // [16][8192][1024]
    const __nv_bfloat16* __restrict__ wv,
    __nv_bfloat16* __restrict__ ao)
{
    extern __shared__ char smem[];
    uint32_t sb = smem_u32(smem);
    int tid = threadIdx.x;
    int lane = tid & 31, wid = tid >> 5;
    int wm = wid & 1, wn = wid >> 1;
    int mt = blockIdx.x, h = blockIdx.y;

    const __nv_bfloat16* hmA = hm + ((size_t)h * MQ + (size_t)mt * 128) * DD;
    const __nv_bfloat16* Bg = wv + (size_t)h * 64 * DD;

    float acc[4][4][4];
    #pragma unroll
    for (int i = 0; i < 4; i++)
        #pragma unroll
        for (int j = 0; j < 4; j++)
            #pragma unroll
            for (int r = 0; r < 4; r++) acc[i][j][r] = 0.f;

    #pragma unroll
    for (int s = 0; s < NSTAGE - 1; s++) {
        vm_load_stage(sb, s, hmA, Bg, s * KC, tid);
        CP_COMMIT();
    }

    for (int s = 0; s < KSTAGES; s++) {
        if (s <= KSTAGES - 3)      asm volatile("cp.async.wait_group 2;" ::: "memory");
        else if (s == KSTAGES - 2) asm volatile("cp.async.wait_group 1;" ::: "memory");
        else                       asm volatile("cp.async.wait_group 0;" ::: "memory");
        __syncthreads();

        if (s + NSTAGE - 1 < KSTAGES) {
            vm_load_stage(sb, (s + NSTAGE - 1) & (NSTAGE - 1), hmA, Bg,
                          (s + NSTAGE - 1) * KC, tid);
            CP_COMMIT();
        }

        int buf = s & (NSTAGE - 1);
        uint32_t abase = sb + buf * VSTAGE_BYTES;
        uint32_t bbase = abase + VA_BYTES;
        #pragma unroll
        for (int k16 = 0; k16 < 4; k16++) {
            uint32_t af[4][4];
            #pragma unroll
            for (int i = 0; i < 4; i++) {
                int row = wm * 64 + i * 16 + (lane & 15);
                uint32_t off = (uint32_t)(row * 128 + k16 * 32 + (lane >> 4) * 16);
                ldmatrix_x4(af[i], abase + SWZ128(off));
            }
            uint32_t bfr[2][4];
            #pragma unroll
            for (int j2 = 0; j2 < 2; j2++) {
                int nrow = wn * 32 + j2 * 16 + (lane & 7) + ((lane >> 4) << 3);
                uint32_t off = (uint32_t)(nrow * 128 + k16 * 32 + ((lane >> 3) & 1) * 16);
                ldmatrix_x4(bfr[j2], bbase + SWZ128(off));
            }
            #pragma unroll
            for (int i = 0; i < 4; i++)
                #pragma unroll
                for (int j = 0; j < 4; j++)
                    mma16816(acc[i][j], af[i], bfr[j >> 1][(j & 1) * 2], bfr[j >> 1][(j & 1) * 2 + 1]);
        }
        __syncthreads();
    }

    int rbase = mt * 128 + wm * 64 + (lane >> 2);
    int cbase = wn * 32 + (lane & 3) * 2;
    #pragma unroll
    for (int i = 0; i < 4; i++) {
        #pragma unroll
        for (int half = 0; half < 2; half++) {
            int row = rbase + i * 16 + half * 8;
            size_t base = (size_t)row * DD + h * 64 + cbase;
            #pragma unroll
            for (int j = 0; j < 4; j++) {
                uint32_t p = pack_bf16(acc[i][j][half * 2 + 0], acc[i][j][half * 2 + 1]);
                *reinterpret_cast<uint32_t*>(ao + base + j * 8) = p;
            }
        }
    }
}

// ---------------- launch ----------------
extern "C" void kernel_launch(void* const* d_in, const int* in_sizes, int n_in,
                              void* d_out, int out_size) {
    const float* cur  = (const float*)d_in[0];
    const float* hist = (const float*)d_in[1];
    const float* Wq   = (const float*)d_in[2];
    const float* Wk   = (const float*)d_in[3];
    const float* Wv   = (const float*)d_in[4];
    const float* Wo   = (const float*)d_in[5];
    float* out = (float*)d_out;

    __nv_bfloat16 *p_cur, *p_wq, *p_wkt, *p_wv, *p_wo, *p_q, *p_qk, *p_hm, *p_ao;
    cudaGetSymbolAddress((void**)&p_cur, g_cur);
    cudaGetSymbolAddress((void**)&p_wq, g_wq);
    cudaGetSymbolAddress((void**)&p_wkt, g_wkt);
    cudaGetSymbolAddress((void**)&p_wv, g_wv);
    cudaGetSymbolAddress((void**)&p_wo, g_wo);
    cudaGetSymbolAddress((void**)&p_q, g_q);
    cudaGetSymbolAddress((void**)&p_qk, g_qk);
    cudaGetSymbolAddress((void**)&p_hm, g_hm);
    cudaGetSymbolAddress((void**)&p_ao, g_ao);

    cudaFuncSetAttribute(gemm_hmma<false>, cudaFuncAttributeMaxDynamicSharedMemorySize, GEMM_SMEM);
    cudaFuncSetAttribute(gemm_hmma<true>,  cudaFuncAttributeMaxDynamicSharedMemorySize, GEMM_SMEM);
    cudaFuncSetAttribute(qk_fold2, cudaFuncAttributeMaxDynamicSharedMemorySize, QF_SMEM);
    cudaFuncSetAttribute(attn_fused2, cudaFuncAttributeMaxDynamicSharedMemorySize, ATT_SMEM);
    cudaFuncSetAttribute(vm_gemm, cudaFuncAttributeMaxDynamicSharedMemorySize, VM_SMEM);

    // conversions (one kernel) + Wk transpose
    {
        int nchunks = CUR_CHUNKS + 3 * W_CHUNKS;
        cvt_all<<<(nchunks + 255) / 256, 256>>>(cur, Wq, Wv, Wo, p_cur, p_wq, p_wv, p_wo);
        transp_wk<<<256, 256>>>(Wk, p_wkt);
    }

    // Q = cur @ Wq^T
    gemm_hmma<false><<<(MQ / TM) * 4, 256, GEMM_SMEM>>>(p_cur, p_wq, p_q, nullptr, nullptr);

    // qk fold: per-head q_h @ Wk_h (pipelined copy-out)
    {
        dim3 grid(MQ / 128, HH);
        qk_fold2<<<grid, 256, QF_SMEM>>>(p_q, p_wkt, p_qk);
    }

    // fused attention -> hm (head-major)
    attn_fused2<<<MQ, 128, ATT_SMEM>>>(hist, p_qk, p_hm);

    // vm: per-head hm_h @ Wv_h^T -> ao
    {
        dim3 grid(MQ / 128, HH);
        vm_gemm<<<grid, 128, VM_SMEM>>>(p_hm, p_wv, p_ao);
    }

    // out = cur + ao @ Wo^T
    gemm_hmma<true><<<(MQ / TM) * 4, 256, GEMM_SMEM>>>(p_ao, p_wo, nullptr, out, cur);
}